// round 1
// baseline (speedup 1.0000x reference)
#include <cuda_runtime.h>
#include <cuda_bf16.h>

#define NEGC 1000000000000.0f

#define B_ 8
#define L_ 512
#define H_ 768
#define O_ 12

// Scratch (allocation-free rule: __device__ globals)
__device__ float g_T[(size_t)B_ * L_ * O_ * H_];   // 151 MB: T[b,x,o,j]
__device__ float g_lini[B_ * L_ * O_];
__device__ float g_linj[B_ * L_ * O_];

// ---------------------------------------------------------------------------
// lin_i = X @ W2[:H], lin_j = X @ W2[H:2H]   (tiny: ~150 MFLOP)
// ---------------------------------------------------------------------------
__global__ void lin_kernel(const float* __restrict__ X, const float* __restrict__ W2) {
    int idx = blockIdx.x * blockDim.x + threadIdx.x;
    if (idx >= B_ * L_ * O_) return;
    int row = idx / O_;
    int o   = idx % O_;
    const float* xr = X + (size_t)row * H_;
    float si = 0.f, sj = 0.f;
#pragma unroll 4
    for (int k = 0; k < H_; k++) {
        float xv = xr[k];
        si = fmaf(xv, W2[k * O_ + o], si);
        sj = fmaf(xv, W2[(H_ + k) * O_ + o], sj);
    }
    g_lini[idx] = si;
    g_linj[idx] = sj;
}

// ---------------------------------------------------------------------------
// Stage 1: g_T[(b x), (o j)] = X[(b x), i] * W1[i, (o j)]
// NN SGEMM 128x128x8, 256 threads, 8x8 microtile.
// M=4096, N=9216, K=768. grid = (72, 32)
// ---------------------------------------------------------------------------
__global__ __launch_bounds__(256, 2) void sgemm_stage1(
    const float* __restrict__ A, const float* __restrict__ Bm)
{
    const int K = H_, lda = H_, ldb = O_ * H_, ldc = O_ * H_;
    __shared__ float As[8][128];
    __shared__ float Bs[8][128];
    int tid  = threadIdx.x;
    int bm   = blockIdx.y * 128, bn = blockIdx.x * 128;
    int warp = tid >> 5, lane = tid & 31;
    int wm = warp >> 1, wn = warp & 1;   // 4x2 warp grid: 32 rows x 64 cols per warp
    int r  = lane >> 3, c  = lane & 7;   // 4x8 lanes
    int row0 = wm * 32 + r * 4;          // rows: row0+0..3 and row0+16..19
    int col0 = wn * 64 + c * 4;          // cols: col0+0..3 and col0+32..35

    int arow = tid >> 1, acol = (tid & 1) * 4;       // A: 128 rows x 8 k
    int brow = warp,     bcol = lane * 4;            // B: 8 k x 128 cols
    const float* Aptr = A  + (size_t)(bm + arow) * lda + acol;
    const float* Bptr = Bm + (size_t)brow * ldb + bn + bcol;

    float acc[8][8] = {};
    float4 aR = *(const float4*)Aptr;
    float4 bR = *(const float4*)Bptr;

    for (int kt = 0; kt < K; kt += 8) {
        __syncthreads();
        As[acol + 0][arow] = aR.x; As[acol + 1][arow] = aR.y;
        As[acol + 2][arow] = aR.z; As[acol + 3][arow] = aR.w;
        *(float4*)&Bs[brow][bcol] = bR;
        __syncthreads();
        if (kt + 8 < K) {
            aR = *(const float4*)(Aptr + kt + 8);
            bR = *(const float4*)(Bptr + (size_t)(kt + 8) * ldb);
        }
#pragma unroll
        for (int k = 0; k < 8; k++) {
            float4 a0 = *(const float4*)&As[k][row0];
            float4 a1 = *(const float4*)&As[k][row0 + 16];
            float4 b0 = *(const float4*)&Bs[k][col0];
            float4 b1 = *(const float4*)&Bs[k][col0 + 32];
            float av[8] = {a0.x, a0.y, a0.z, a0.w, a1.x, a1.y, a1.z, a1.w};
            float bv[8] = {b0.x, b0.y, b0.z, b0.w, b1.x, b1.y, b1.z, b1.w};
#pragma unroll
            for (int i = 0; i < 8; i++)
#pragma unroll
                for (int j = 0; j < 8; j++)
                    acc[i][j] = fmaf(av[i], bv[j], acc[i][j]);
        }
    }

#pragma unroll
    for (int i = 0; i < 8; i++) {
        int row = bm + row0 + ((i < 4) ? i : 12 + i);   // i>=4 -> row0+16+(i-4)
        float4 v0 = make_float4(acc[i][0], acc[i][1], acc[i][2], acc[i][3]);
        float4 v1 = make_float4(acc[i][4], acc[i][5], acc[i][6], acc[i][7]);
        *(float4*)&g_T[(size_t)row * ldc + bn + col0]      = v0;
        *(float4*)&g_T[(size_t)row * ldc + bn + col0 + 32] = v1;
    }
}

// ---------------------------------------------------------------------------
// Stage 2: per (b,o): C[x,y] = sum_j T[b,x,o,j] * X[b,y,j]  (NT SGEMM)
// then fused epilogue: + lin_i + lin_j + bias, masks, causal -NEG, write out.
// M=N=512, K=768, grid=(4,4,96)
// ---------------------------------------------------------------------------
__global__ __launch_bounds__(256, 2) void sgemm_stage2(
    const float* __restrict__ X, const float* __restrict__ W2,
    const int* __restrict__ mask, float* __restrict__ out)
{
    const int K = H_;
    __shared__ float As[8][128];
    __shared__ float Bs[8][128];
    int tid = threadIdx.x;
    int bo = blockIdx.z;
    int b = bo / O_, o = bo % O_;
    int bm = blockIdx.y * 128;   // x tile
    int bn = blockIdx.x * 128;   // y tile
    int warp = tid >> 5, lane = tid & 31;
    int wm = warp >> 1, wn = warp & 1;
    int r  = lane >> 3, c  = lane & 7;
    int row0 = wm * 32 + r * 4;
    int col0 = wn * 64 + c * 4;

    int arow = tid >> 1, acol = (tid & 1) * 4;
    // A row x: stride O_*H_ through T;  B row y: stride H_ through X
    const float* Aptr = g_T + ((size_t)(b * L_ + bm + arow) * O_ + o) * H_ + acol;
    const float* Bptr = X + (size_t)(b * L_ + bn + arow) * H_ + acol;

    float acc[8][8] = {};
    float4 aR = *(const float4*)Aptr;
    float4 bR = *(const float4*)Bptr;

    for (int kt = 0; kt < K; kt += 8) {
        __syncthreads();
        As[acol + 0][arow] = aR.x; As[acol + 1][arow] = aR.y;
        As[acol + 2][arow] = aR.z; As[acol + 3][arow] = aR.w;
        Bs[acol + 0][arow] = bR.x; Bs[acol + 1][arow] = bR.y;
        Bs[acol + 2][arow] = bR.z; Bs[acol + 3][arow] = bR.w;
        __syncthreads();
        if (kt + 8 < K) {
            aR = *(const float4*)(Aptr + kt + 8);
            bR = *(const float4*)(Bptr + kt + 8);
        }
#pragma unroll
        for (int k = 0; k < 8; k++) {
            float4 a0 = *(const float4*)&As[k][row0];
            float4 a1 = *(const float4*)&As[k][row0 + 16];
            float4 b0 = *(const float4*)&Bs[k][col0];
            float4 b1 = *(const float4*)&Bs[k][col0 + 32];
            float av[8] = {a0.x, a0.y, a0.z, a0.w, a1.x, a1.y, a1.z, a1.w};
            float bv[8] = {b0.x, b0.y, b0.z, b0.w, b1.x, b1.y, b1.z, b1.w};
#pragma unroll
            for (int i = 0; i < 8; i++)
#pragma unroll
                for (int j = 0; j < 8; j++)
                    acc[i][j] = fmaf(av[i], bv[j], acc[i][j]);
        }
    }

    // Fused epilogue
    float bias = W2[2 * H_ * O_ + o];
    int   my[8]; float lj[8]; int ys[8];
#pragma unroll
    for (int j = 0; j < 8; j++) {
        int y = bn + col0 + ((j < 4) ? j : 28 + j);   // j>=4 -> col0+32+(j-4)
        ys[j] = y;
        my[j] = mask[b * L_ + y];
        lj[j] = g_linj[(b * L_ + y) * O_ + o];
    }
    size_t outbase = (size_t)bo * L_ * L_;
#pragma unroll
    for (int i = 0; i < 8; i++) {
        int x  = bm + row0 + ((i < 4) ? i : 12 + i);
        int mx = mask[b * L_ + x];
        float li = g_lini[(b * L_ + x) * O_ + o];
        float* orow = out + outbase + (size_t)x * L_;
#pragma unroll
        for (int j = 0; j < 8; j++) {
            float v = acc[i][j] + li + lj[j] + bias;
            if (!mx)       v = -NEGC;
            if (!my[j])    v = -NEGC;
            if (ys[j] < x) v -= NEGC;
            orow[ys[j]] = v;
        }
    }
}

// ---------------------------------------------------------------------------
extern "C" void kernel_launch(void* const* d_in, const int* in_sizes, int n_in,
                              void* d_out, int out_size) {
    const float* inputs = nullptr;
    const float* w1 = nullptr;
    const float* w2 = nullptr;
    const int*   mask = nullptr;
    for (int i = 0; i < n_in; i++) {
        if      (in_sizes[i] == B_ * L_ * H_)     inputs = (const float*)d_in[i];
        else if (in_sizes[i] == H_ * O_ * H_)     w1     = (const float*)d_in[i];
        else if (in_sizes[i] == (2 * H_ + 1) * O_) w2    = (const float*)d_in[i];
        else if (in_sizes[i] == B_ * L_)          mask   = (const int*)d_in[i];
    }
    float* out = (float*)d_out;

    lin_kernel<<<(B_ * L_ * O_ + 255) / 256, 256>>>(inputs, w2);
    sgemm_stage1<<<dim3((O_ * H_) / 128, (B_ * L_) / 128), 256>>>(inputs, w1);
    sgemm_stage2<<<dim3(L_ / 128, L_ / 128, B_ * O_), 256>>>(inputs, w2, mask, out);
}

// round 2
// speedup vs baseline: 9.1396x; 9.1396x over previous
#include <cuda_runtime.h>
#include <cuda_bf16.h>
#include <cstdint>

#define NEGC 1000000000000.0f
#define B_ 8
#define L_ 512
#define H_ 768
#define O_ 12
#define NN_ (O_*H_)   // 9216
#define ML_ (B_*L_)   // 4096

// Scratch (__device__ globals per allocation rules)
__device__ __nv_bfloat16 g_Xb[(size_t)ML_*H_];
__device__ __nv_bfloat16 g_W1t[(size_t)NN_*H_];
__device__ __nv_bfloat16 g_Tb[(size_t)ML_*NN_];     // 75.5 MB bf16
__device__ float g_lini[ML_*O_];
__device__ float g_linj[ML_*O_];

__device__ __forceinline__ uint32_t swz(uint32_t off){ return off ^ ((off>>3)&0x70); }

__device__ __forceinline__ void cp16(uint32_t saddr, const void* g){
    asm volatile("cp.async.cg.shared.global [%0], [%1], 16;\n" :: "r"(saddr), "l"(g));
}

#define LDM4(d0,d1,d2,d3,addr) \
  asm volatile("ldmatrix.sync.aligned.m8n8.x4.shared.b16 {%0,%1,%2,%3}, [%4];\n" \
    : "=r"(d0),"=r"(d1),"=r"(d2),"=r"(d3) : "r"(addr))

#define MMA16816(c,a0,a1,a2,a3,b0,b1) \
  asm volatile("mma.sync.aligned.m16n8k16.row.col.f32.bf16.bf16.f32 " \
    "{%0,%1,%2,%3}, {%4,%5,%6,%7}, {%8,%9}, {%0,%1,%2,%3};\n" \
    : "+f"(c[0]),"+f"(c[1]),"+f"(c[2]),"+f"(c[3]) \
    : "r"(a0),"r"(a1),"r"(a2),"r"(a3),"r"(b0),"r"(b1))

// ---------------------------------------------------------------------------
// X fp32 -> bf16 (elementwise, vectorized)
// ---------------------------------------------------------------------------
__global__ void conv_x(const float* __restrict__ X){
    int i = blockIdx.x*256 + threadIdx.x;          // 4 floats each
    float4 v = ((const float4*)X)[i];
    ((__nv_bfloat162*)g_Xb)[2*i]   = __floats2bfloat162_rn(v.x, v.y);
    ((__nv_bfloat162*)g_Xb)[2*i+1] = __floats2bfloat162_rn(v.z, v.w);
}

// ---------------------------------------------------------------------------
// W1[i][o*H+j] fp32 -> W1t[o*H+j][i] bf16 (tiled transpose)
// ---------------------------------------------------------------------------
__global__ void conv_w1(const float* __restrict__ W1){
    __shared__ float t[32][33];
    int n0 = blockIdx.x*32, i0 = blockIdx.y*32;
    int tx = threadIdx.x, ty = threadIdx.y;        // (32, 8)
#pragma unroll
    for (int r = 0; r < 4; r++)
        t[ty+8*r][tx] = W1[(size_t)(i0+ty+8*r)*NN_ + n0+tx];
    __syncthreads();
#pragma unroll
    for (int r = 0; r < 4; r++)
        g_W1t[(size_t)(n0+ty+8*r)*H_ + i0+tx] = __float2bfloat16_rn(t[tx][ty+8*r]);
}

// ---------------------------------------------------------------------------
// lin_i / lin_j: warp-per-row, X read exactly once
// ---------------------------------------------------------------------------
__global__ void lin_kernel(const float* __restrict__ X, const float* __restrict__ W2){
    int warp = (blockIdx.x*blockDim.x + threadIdx.x) >> 5;
    int lane = threadIdx.x & 31;
    if (warp >= ML_) return;
    const float* xr = X + (size_t)warp*H_;
    float si[O_] = {}, sj[O_] = {};
    for (int k = lane; k < H_; k += 32){
        float xv = xr[k];
        const float* wa = W2 + k*O_;
        const float* wb = W2 + (H_+k)*O_;
#pragma unroll
        for (int o = 0; o < O_; o++){
            si[o] = fmaf(xv, wa[o], si[o]);
            sj[o] = fmaf(xv, wb[o], sj[o]);
        }
    }
#pragma unroll
    for (int o = 0; o < O_; o++){
#pragma unroll
        for (int off = 16; off; off >>= 1){
            si[o] += __shfl_xor_sync(0xFFFFFFFFu, si[o], off);
            sj[o] += __shfl_xor_sync(0xFFFFFFFFu, sj[o], off);
        }
    }
    if (lane == 0){
#pragma unroll
        for (int o = 0; o < O_; o++){
            g_lini[warp*O_ + o] = si[o];
            g_linj[warp*O_ + o] = sj[o];
        }
    }
}

// ---------------------------------------------------------------------------
// bf16 NT tensor-core GEMM, 128x128x64 tiles, cp.async double-buffered.
// STAGE 1: C[(b x)][(o j)] = Xb @ W1t^T  -> g_Tb (bf16)
// STAGE 2: per (b,o): C[x][y] = T[b,x,o,:] @ Xb[b,y,:]^T, fused epilogue -> out
// ---------------------------------------------------------------------------
template<int STAGE>
__global__ __launch_bounds__(256,2) void mma_gemm(
    const float* __restrict__ W2, const int* __restrict__ mask, float* __restrict__ out)
{
    extern __shared__ __align__(1024) char smem[];
    uint32_t sbase = (uint32_t)__cvta_generic_to_shared(smem);
    int tid = threadIdx.x, lane = tid & 31, warp = tid >> 5;
    int wm = warp >> 1, wn = warp & 1;             // 4x2 warps, 32x64 each

    int bm, bn, b = 0, o = 0, bo = 0;
    const __nv_bfloat16 *Ag, *Bg;
    size_t lda, ldb;
    if (STAGE == 1){
        bm = blockIdx.y*128; bn = blockIdx.x*128;
        Ag = g_Xb  + (size_t)bm*H_; lda = H_;
        Bg = g_W1t + (size_t)bn*H_; ldb = H_;
    } else {
        bo = blockIdx.z; b = bo / O_; o = bo % O_;
        bm = blockIdx.y*128; bn = blockIdx.x*128;
        Ag = g_Tb + (size_t)(b*L_+bm)*NN_ + o*H_; lda = NN_;
        Bg = g_Xb + (size_t)(b*L_+bn)*H_;         ldb = H_;
    }

    int lr = tid >> 3, lc = tid & 7;               // loader: 32 rows x 8 chunks
    const __nv_bfloat16* Agl = Ag + (size_t)lr*lda + lc*8;
    const __nv_bfloat16* Bgl = Bg + (size_t)lr*ldb + lc*8;

    float acc[2][8][4];
#pragma unroll
    for (int i=0;i<2;i++) for (int j=0;j<8;j++) for (int k=0;k<4;k++) acc[i][j][k]=0.f;

    // prologue: chunk 0 -> buf 0
    {
        uint32_t ab = sbase, bb = sbase + 16384;
#pragma unroll
        for (int q = 0; q < 4; q++){
            uint32_t so = swz((lr+32*q)*128 + lc*16);
            cp16(ab + so, Agl + (size_t)(32*q)*lda);
            cp16(bb + so, Bgl + (size_t)(32*q)*ldb);
        }
        asm volatile("cp.async.commit_group;\n");
    }

    int buf = 0;
    int rsel = lane & 15, hi = lane >> 4;
    for (int kt = 0; kt < H_; kt += 64){
        if (kt + 64 < H_){
            uint32_t ab = sbase + (buf^1)*32768, bb = ab + 16384;
#pragma unroll
            for (int q = 0; q < 4; q++){
                uint32_t so = swz((lr+32*q)*128 + lc*16);
                cp16(ab + so, Agl + (size_t)(32*q)*lda + (kt+64));
                cp16(bb + so, Bgl + (size_t)(32*q)*ldb + (kt+64));
            }
            asm volatile("cp.async.commit_group;\n");
            asm volatile("cp.async.wait_group 1;\n");
        } else {
            asm volatile("cp.async.wait_group 0;\n");
        }
        __syncthreads();

        uint32_t ab = sbase + buf*32768, bb = ab + 16384;
#pragma unroll
        for (int ks = 0; ks < 4; ks++){
            uint32_t a[2][4], bf[4][4];
#pragma unroll
            for (int mt = 0; mt < 2; mt++){
                uint32_t off = (wm*32 + mt*16 + rsel)*128 + ks*32 + hi*16;
                LDM4(a[mt][0],a[mt][1],a[mt][2],a[mt][3], ab + swz(off));
            }
#pragma unroll
            for (int p = 0; p < 4; p++){
                uint32_t off = (wn*64 + p*16 + rsel)*128 + ks*32 + hi*16;
                LDM4(bf[p][0],bf[p][1],bf[p][2],bf[p][3], bb + swz(off));
            }
#pragma unroll
            for (int mt = 0; mt < 2; mt++)
#pragma unroll
                for (int nt = 0; nt < 8; nt++)
                    MMA16816(acc[mt][nt], a[mt][0],a[mt][1],a[mt][2],a[mt][3],
                             bf[nt>>1][nt&1], bf[nt>>1][2+(nt&1)]);
        }
        __syncthreads();
        buf ^= 1;
    }

    int g = lane >> 2, t2 = (lane & 3)*2;
    if (STAGE == 1){
#pragma unroll
        for (int mt = 0; mt < 2; mt++){
            int row = bm + wm*32 + mt*16 + g;
#pragma unroll
            for (int nt = 0; nt < 8; nt++){
                int col = bn + wn*64 + nt*8 + t2;
                *(__nv_bfloat162*)&g_Tb[(size_t)row*NN_ + col] =
                    __floats2bfloat162_rn(acc[mt][nt][0], acc[mt][nt][1]);
                *(__nv_bfloat162*)&g_Tb[(size_t)(row+8)*NN_ + col] =
                    __floats2bfloat162_rn(acc[mt][nt][2], acc[mt][nt][3]);
            }
        }
    } else {
        float bias = W2[2*H_*O_ + o];
        int myv[16]; float lj[16];
#pragma unroll
        for (int nt = 0; nt < 8; nt++){
            int y = bn + wn*64 + nt*8 + t2;
            myv[2*nt]   = mask[b*L_+y];
            myv[2*nt+1] = mask[b*L_+y+1];
            lj[2*nt]    = g_linj[(b*L_+y)*O_+o];
            lj[2*nt+1]  = g_linj[(b*L_+y+1)*O_+o];
        }
#pragma unroll
        for (int mt = 0; mt < 2; mt++)
#pragma unroll
            for (int half = 0; half < 2; half++){
                int x  = bm + wm*32 + mt*16 + g + half*8;
                int mx = mask[b*L_+x];
                float li = g_lini[(b*L_+x)*O_+o] + bias;
                float* orow = out + (size_t)bo*L_*L_ + (size_t)x*L_;
#pragma unroll
                for (int nt = 0; nt < 8; nt++){
                    int y = bn + wn*64 + nt*8 + t2;
                    float v0 = acc[mt][nt][half*2+0] + li + lj[2*nt];
                    float v1 = acc[mt][nt][half*2+1] + li + lj[2*nt+1];
                    if (!mx)         { v0 = -NEGC; v1 = -NEGC; }
                    if (!myv[2*nt])    v0 = -NEGC;
                    if (!myv[2*nt+1])  v1 = -NEGC;
                    if (y   < x)       v0 -= NEGC;
                    if (y+1 < x)       v1 -= NEGC;
                    *(float2*)&orow[y] = make_float2(v0, v1);
                }
            }
    }
}

// ---------------------------------------------------------------------------
extern "C" void kernel_launch(void* const* d_in, const int* in_sizes, int n_in,
                              void* d_out, int out_size) {
    const float* inputs = nullptr;
    const float* w1 = nullptr;
    const float* w2 = nullptr;
    const int*   mask = nullptr;
    for (int i = 0; i < n_in; i++) {
        if      (in_sizes[i] == B_*L_*H_)      inputs = (const float*)d_in[i];
        else if (in_sizes[i] == H_*O_*H_)      w1     = (const float*)d_in[i];
        else if (in_sizes[i] == (2*H_+1)*O_)   w2     = (const float*)d_in[i];
        else if (in_sizes[i] == B_*L_)         mask   = (const int*)d_in[i];
    }
    float* out = (float*)d_out;

    cudaFuncSetAttribute(mma_gemm<1>, cudaFuncAttributeMaxDynamicSharedMemorySize, 65536);
    cudaFuncSetAttribute(mma_gemm<2>, cudaFuncAttributeMaxDynamicSharedMemorySize, 65536);

    conv_x<<<(ML_*H_/4 + 255)/256, 256>>>(inputs);
    conv_w1<<<dim3(NN_/32, H_/32), dim3(32,8)>>>(w1);
    lin_kernel<<<ML_/8, 256>>>(inputs, w2);
    mma_gemm<1><<<dim3(NN_/128, ML_/128), 256, 65536>>>(w2, mask, out);
    mma_gemm<2><<<dim3(L_/128, L_/128, B_*O_), 256, 65536>>>(w2, mask, out);
}